// round 15
// baseline (speedup 1.0000x reference)
#include <cuda_runtime.h>
#include <math.h>
#include <stdint.h>

// Problem dims (fixed by setup_inputs)
#define BB 4
#define LL 2048
#define DD 1024
#define MM (BB*LL)   // 8192
#define NCH (BB*DD)  // 4096 channels
#define CH  32       // scan chunks
#define CL  (LL/CH)  // 64 steps per chunk

// Scratch (device globals: allowed; runtime alloc is not)
__device__ float g_lam[(size_t)MM*DD];
__device__ float g_b[(size_t)MM*DD];
__device__ float g_alpha[(size_t)MM*DD];
__device__ float g_f[(size_t)MM*DD];
__device__ float g_s[(size_t)MM*DD];
__device__ float g_h[(size_t)MM*DD];
// tf32-rounded operand copies (composed RNA rounding -> rel_err 2.8e-4)
__device__ float g_xr[(size_t)MM*DD];
__device__ float g_Pr[(size_t)DD*DD];
__device__ float g_Wbr[(size_t)DD*DD];
__device__ float g_War[(size_t)DD*DD];
__device__ float g_Wrr[(size_t)DD*3*DD];
__device__ float g_Wpr[(size_t)DD*DD];
// scan chunk maps + entry states
__device__ float p_A[CH*NCH], p_B0[CH*NCH], p_C[CH*NCH], p_D[CH*NCH], p_E[CH*NCH];
__device__ float e_f[CH*NCH], e_s[CH*NCH];

// ---------------- helpers ----------------
__device__ __forceinline__ uint32_t smem_u32(const void* p) {
    uint32_t a;
    asm("{ .reg .u64 t; cvta.to.shared.u64 t, %1; cvt.u32.u64 %0, t; }" : "=r"(a) : "l"(p));
    return a;
}

__device__ __forceinline__ uint32_t f2tf32(float f) {
    uint32_t r;
    asm("cvt.rna.tf32.f32 %0, %1;" : "=r"(r) : "f"(f));
    return r;
}

__device__ __forceinline__ void mma8(float c[4], const uint32_t a[4], const uint32_t b[2]) {
    asm volatile(
        "mma.sync.aligned.m16n8k8.row.col.f32.tf32.tf32.f32 "
        "{%0,%1,%2,%3},{%4,%5,%6,%7},{%8,%9},{%0,%1,%2,%3};\n"
        : "+f"(c[0]), "+f"(c[1]), "+f"(c[2]), "+f"(c[3])
        : "r"(a[0]), "r"(a[1]), "r"(a[2]), "r"(a[3]), "r"(b[0]), "r"(b[1]));
}

#define LDSM4(r0, r1, r2, r3, addr)                                            \
    asm volatile("ldmatrix.sync.aligned.m8n8.x4.shared.b16 {%0,%1,%2,%3},[%4];" \
        : "=r"(r0), "=r"(r1), "=r"(r2), "=r"(r3) : "r"(addr))

#define CP16(dst, src)                                                         \
    asm volatile("cp.async.cg.shared.global [%0], [%1], 16;"                   \
                 :: "r"(dst), "l"(src) : "memory")
#define CP_COMMIT() asm volatile("cp.async.commit_group;" ::: "memory")
#define CP_WAIT1()  asm volatile("cp.async.wait_group 1;" ::: "memory")
#define CP_WAIT0()  asm volatile("cp.async.wait_group 0;" ::: "memory")

__device__ __forceinline__ float fsig(float v) { return 1.0f / (1.0f + __expf(-v)); }

// ---------------- GEMM config ----------------
constexpr int BM = 128, BN = 128, BK = 32, STAGES = 3;
constexpr int ROWB   = 144;             // bytes per smem row (32 u32 + 4 pad)
constexpr int ATILE  = 128 * ROWB;      // 18432 B
constexpr int STAGEB = 2 * ATILE;       // A+B per stage (36864)
constexpr int SMEMB  = STAGES * STAGEB; // 110592 B -> 2 CTAs/SM

// MODE 0: Y = xr @ Wr^T, Wr in {g_Pr(z0), g_Wbr(z1), g_War(z2)} -> lam/b/alpha
// MODE 1: rho = sigmoid([f,s,xr] @ g_Wrr^T + b); g_h = s + rho*(f-s)
// MODE 2: out = x + res_scale * (g_h @ g_Wpr^T)
template<int MODE>
__global__ void __launch_bounds__(256, 2)
rsp_gemm(const float* __restrict__ x,
         const float* __restrict__ bias0, const float* __restrict__ bias2,
         const float* __restrict__ rho_b, const float* __restrict__ res_scale,
         float* __restrict__ dout)
{
    extern __shared__ char smem[];
    const uint32_t sb = smem_u32(smem);
    const int t = threadIdx.x;
    const int lane = t & 31, wid = t >> 5;
    const int bm = blockIdx.y * BM;
    const int bn = blockIdx.x * BN;

    constexpr int K    = (MODE == 1) ? 3072 : 1024;
    constexpr int KT   = K / BK;
    constexpr int LDB_ = (MODE == 1) ? 3072 : 1024;

    const float* Wsel;
    if (MODE == 0)
        Wsel = (blockIdx.z == 0) ? g_Pr : ((blockIdx.z == 1) ? g_Wbr : g_War);
    else if (MODE == 1)
        Wsel = g_Wrr;
    else
        Wsel = g_Wpr;

    // ---- async loader mapping: 256 threads, 2 threads per row, 4x16B each
    const int lrow = t >> 1;           // 0..127
    const int lch  = (t & 1) * 4;      // element chunk base (x4 -> 0 or 16 elts)
    const uint32_t adst0 = sb + (uint32_t)lrow * ROWB + (uint32_t)lch * 16;
    const uint32_t bdst0 = adst0 + ATILE;
    const float* bsrc_row = Wsel + (size_t)(bn + lrow) * LDB_ + lch * 4;

    auto load_stage = [&](int kt) {
        const int st = kt % STAGES;
        const int k0 = kt * BK;
        const float* asrc; int acol = k0;
        if (MODE == 1) {
            if (k0 < 1024)      { asrc = g_f; }
            else if (k0 < 2048) { asrc = g_s;  acol = k0 - 1024; }
            else                { asrc = g_xr; acol = k0 - 2048; }
        } else if (MODE == 0) { asrc = g_xr; }
        else                  { asrc = g_h; }
        const float* ap = asrc + (size_t)(bm + lrow) * 1024 + acol + lch * 4;
        const uint32_t ad = adst0 + st * STAGEB;
#pragma unroll
        for (int i = 0; i < 4; i++) CP16(ad + i * 16, ap + i * 4);
        const float* bp = bsrc_row + k0;
        const uint32_t bd = bdst0 + st * STAGEB;
#pragma unroll
        for (int i = 0; i < 4; i++) CP16(bd + i * 16, bp + i * 4);
    };

    // ---- ldmatrix per-lane address bases
    const int wm = (wid >> 2) * 64;    // warp tile 64x32
    const int wn = (wid & 3) * 32;
    uint32_t aoff[4], boff[2];
    {
        const int ar = wm + ((lane >> 3) & 1) * 8 + (lane & 7);
        const uint32_t aq = (uint32_t)(lane >> 4) * 16;
#pragma unroll
        for (int mi = 0; mi < 4; mi++)
            aoff[mi] = sb + (uint32_t)(ar + mi * 16) * ROWB + aq;
        const int br = wn + ((lane >> 4) & 1) * 8 + (lane & 7);
        const uint32_t bq = (uint32_t)((lane >> 3) & 1) * 16;
#pragma unroll
        for (int np = 0; np < 2; np++)
            boff[np] = sb + ATILE + (uint32_t)(br + np * 16) * ROWB + bq;
    }

    float c[4][4][4];
#pragma unroll
    for (int i = 0; i < 4; i++)
#pragma unroll
        for (int j = 0; j < 4; j++)
#pragma unroll
            for (int r = 0; r < 4; r++) c[i][j][r] = 0.f;

    // fragment double buffers (ks-level software pipeline)
    uint32_t af[2][4][4], bfr[2][4][2];

    auto ldsm_frag = [&](uint32_t stb, int ks, int buf) {
        const uint32_t o = stb + (uint32_t)ks * 32;
#pragma unroll
        for (int mi = 0; mi < 4; mi++)
            LDSM4(af[buf][mi][0], af[buf][mi][1], af[buf][mi][2], af[buf][mi][3],
                  aoff[mi] + o);
#pragma unroll
        for (int np = 0; np < 2; np++) {
            uint32_t r0, r1, r2, r3;
            LDSM4(r0, r1, r2, r3, boff[np] + o);
            bfr[buf][2*np][0]   = r0; bfr[buf][2*np][1]   = r1;
            bfr[buf][2*np+1][0] = r2; bfr[buf][2*np+1][1] = r3;
        }
    };

    // preamble: stages 0 and 1 in flight; fragments for (stage0, ks0) in regs
    load_stage(0); CP_COMMIT();
    load_stage(1); CP_COMMIT();
    CP_WAIT1();          // stage 0 landed
    __syncthreads();     // publish to all warps
    ldsm_frag(0, 0, 0);

    // steady state at top of kt: stage kt in smem (published), stage kt+1
    // committed; fragments (kt, ks0) already in buf (ks parity 0).
    // (R9/R13/R14 structure — measured best across all variants tried.)
#pragma unroll 1
    for (int kt = 0; kt < KT; kt++) {
        const uint32_t stb = (uint32_t)(kt % STAGES) * STAGEB;
#pragma unroll
        for (int ks = 0; ks < 4; ks++) {
            const int cur = ks & 1;
            if (ks < 3) {
                ldsm_frag(stb, ks + 1, cur ^ 1);    // prefetch next ks
            } else {
                // tile boundary, hidden behind the ks=3 MMA block below.
                if (kt + 2 < KT) {
                    load_stage(kt + 2);
                    CP_COMMIT();
                    CP_WAIT1();      // pending <=1 (stage kt+2) => kt+1 landed
                } else {
                    CP_WAIT0();      // tail: drain everything
                }
                __syncthreads();     // publish stage kt+1 across warps
                if (kt + 1 < KT)
                    ldsm_frag((uint32_t)((kt + 1) % STAGES) * STAGEB, 0, cur ^ 1);
            }
#pragma unroll
            for (int mi = 0; mi < 4; mi++)
#pragma unroll
                for (int ni = 0; ni < 4; ni++)
                    mma8(c[mi][ni], af[cur][mi], bfr[cur][ni]);
        }
    }

    // ---------------- epilogue ----------------
    const int g = lane >> 2, tg = lane & 3;
    const float rs = (MODE == 2) ? res_scale[0] : 0.f;
#pragma unroll
    for (int mi = 0; mi < 4; mi++) {
#pragma unroll
        for (int r2 = 0; r2 < 2; r2++) {
            const int m = bm + wm + mi * 16 + g + r2 * 8;
#pragma unroll
            for (int ni = 0; ni < 4; ni++) {
                const int e = bn + wn + ni * 8 + tg * 2;
                const size_t idx = (size_t)m * DD + e;
                const float v0 = c[mi][ni][r2 * 2 + 0];
                const float v1 = c[mi][ni][r2 * 2 + 1];
                if (MODE == 0) {
                    if (blockIdx.z == 0) {
                        float2 bp = *reinterpret_cast<const float2*>(bias0 + e);
                        float l0 = fminf(fmaxf(bp.x + v0, -4.f), 4.f);
                        float l1 = fminf(fmaxf(bp.y + v1, -4.f), 4.f);
                        float2 o;
                        o.x = fminf(fmaxf(__expf(-__expf(l0)), 0.001f), 0.999f);
                        o.y = fminf(fmaxf(__expf(-__expf(l1)), 0.001f), 0.999f);
                        *reinterpret_cast<float2*>(g_lam + idx) = o;
                    } else if (blockIdx.z == 1) {
                        float2 o;
                        o.x = v0 * fsig(v0) + 0.1f * __sinf(v0);
                        o.y = v1 * fsig(v1) + 0.1f * __sinf(v1);
                        *reinterpret_cast<float2*>(g_b + idx) = o;
                    } else {
                        float2 bp = *reinterpret_cast<const float2*>(bias2 + e);
                        float2 o;
                        o.x = fsig(v0 + bp.x);
                        o.y = fsig(v1 + bp.y);
                        *reinterpret_cast<float2*>(g_alpha + idx) = o;
                    }
                } else if (MODE == 1) {
                    float2 bp = *reinterpret_cast<const float2*>(rho_b + e);
                    float2 fv = *reinterpret_cast<const float2*>(g_f + idx);
                    float2 sv = *reinterpret_cast<const float2*>(g_s + idx);
                    float h0 = sv.x + fsig(v0 + bp.x) * (fv.x - sv.x);
                    float h1 = sv.y + fsig(v1 + bp.y) * (fv.y - sv.y);
                    // round at write: feeds the MODE2 GEMM as an A operand
                    uint2 o;
                    o.x = f2tf32(h0); o.y = f2tf32(h1);
                    *reinterpret_cast<uint2*>(g_h + idx) = o;
                } else {
                    float2 xv = *reinterpret_cast<const float2*>(x + idx);
                    float2 o;
                    o.x = xv.x + rs * v0;
                    o.y = xv.y + rs * v1;
                    *reinterpret_cast<float2*>(dout + idx) = o;
                }
            }
        }
    }
}

// ---------------- chunked parallel scan ----------------
// f_t = lam_t*f_{t-1} + b_t ; s_t = (1-a_t)*s_{t-1} + a_t*f_t
// Chunk map: f_out = A*f_in + B0 ; s_out = C*f_in + D*s_in + E
__global__ void __launch_bounds__(256)
scan_p1()
{
    const int ch    = blockIdx.x * 256 + threadIdx.x;  // 0..4095
    const int chunk = blockIdx.y;                       // 0..31
    const int b = ch / DD, d = ch % DD;
    const size_t base = (size_t)b * LL * DD + (size_t)(chunk * CL) * DD + d;

    float aF = 1.f, cF = 0.f, cS = 0.f, dS = 1.f, ee = 0.f;
#pragma unroll 16
    for (int u = 0; u < CL; u++) {
        const size_t i = base + (size_t)u * DD;
        const float lam = g_lam[i];
        const float bv  = g_b[i];
        const float al  = g_alpha[i];
        aF = lam * aF;
        cF = fmaf(lam, cF, bv);
        const float om = 1.f - al;
        cS = fmaf(om, cS, al * aF);
        dS = om * dS;
        ee = fmaf(om, ee, al * cF);
    }
    const int o = chunk * NCH + ch;
    p_A[o] = aF; p_B0[o] = cF; p_C[o] = cS; p_D[o] = dS; p_E[o] = ee;
}

// Pass 2: fold 32 chunk maps per channel, software-prefetched ping-pong.
__global__ void __launch_bounds__(256)
scan_p2(const float* __restrict__ f_prev, const float* __restrict__ s_prev,
        float* __restrict__ dout, int write_tail)
{
    const int ch = blockIdx.x * 256 + threadIdx.x;  // 0..4095
    float f = f_prev[ch], s = s_prev[ch];

    constexpr int U = 8;                   // chunks per batch; CH/U = 4 batches
    float A0[U], B0_[U], C0[U], D0[U], E0[U];
    float A1[U], B1_[U], C1[U], D1[U], E1[U];

#define P2_FETCH(sfx, batch) do {                                              \
        const int base_o = (batch) * U * NCH + ch;                             \
        _Pragma("unroll")                                                      \
        for (int u = 0; u < U; u++) {                                          \
            A##sfx[u]  = p_A [base_o + u * NCH];                               \
            B##sfx##_[u] = p_B0[base_o + u * NCH];                             \
            C##sfx[u]  = p_C [base_o + u * NCH];                               \
            D##sfx[u]  = p_D [base_o + u * NCH];                               \
            E##sfx[u]  = p_E [base_o + u * NCH];                               \
        } } while (0)

#define P2_FOLD(sfx, batch) do {                                               \
        const int base_o = (batch) * U * NCH + ch;                             \
        _Pragma("unroll")                                                      \
        for (int u = 0; u < U; u++) {                                          \
            e_f[base_o + u * NCH] = f;                                         \
            e_s[base_o + u * NCH] = s;                                         \
            const float fn = fmaf(A##sfx[u], f, B##sfx##_[u]);                 \
            s = fmaf(C##sfx[u], f, fmaf(D##sfx[u], s, E##sfx[u]));             \
            f = fn;                                                            \
        } } while (0)

    P2_FETCH(0, 0);
#pragma unroll 1
    for (int p = 0; p < CH / (2 * U); p++) {    // 2 pairs of batches
        P2_FETCH(1, 2 * p + 1);
        P2_FOLD(0, 2 * p);
        if (2 * p + 2 < CH / U) P2_FETCH(0, 2 * p + 2);
        P2_FOLD(1, 2 * p + 1);
    }
#undef P2_FETCH
#undef P2_FOLD

    if (write_tail) {
        dout[(size_t)MM * DD + ch]           = f;   // f_states[:, -1, :]
        dout[(size_t)MM * DD + NCH + ch]     = s;   // s_states[:, -1, :]
    }
}

__global__ void __launch_bounds__(256)
scan_p3()
{
    const int ch    = blockIdx.x * 256 + threadIdx.x;
    const int chunk = blockIdx.y;
    const int b = ch / DD, d = ch % DD;
    const size_t base = (size_t)b * LL * DD + (size_t)(chunk * CL) * DD + d;

    const int o = chunk * NCH + ch;
    float f = e_f[o], s = e_s[o];
#pragma unroll 16
    for (int u = 0; u < CL; u++) {
        const size_t i = base + (size_t)u * DD;
        const float lam = g_lam[i];
        const float bv  = g_b[i];
        const float al  = g_alpha[i];
        f = fmaf(lam, f, bv);
        s = fmaf(al, f - s, s);
        g_f[i] = __uint_as_float(f2tf32(f));
        g_s[i] = __uint_as_float(f2tf32(s));
    }
}

// ---------------- tf32 pre-rounding (3 launches; gemm<0> stays launch #4) --
// 64 B/thread (4x float4): 4 independent loads in flight per thread for MLP,
// 1/4 the CTAs -> less wave overhead on these bandwidth kernels.
__global__ void round_x(const float* __restrict__ src)
{
    const int i0 = (blockIdx.x * blockDim.x + threadIdx.x) * 16;
    float4 v[4];
#pragma unroll
    for (int j = 0; j < 4; j++)
        v[j] = *reinterpret_cast<const float4*>(src + i0 + j * 4);
#pragma unroll
    for (int j = 0; j < 4; j++) {
        uint4 o;
        o.x = f2tf32(v[j].x); o.y = f2tf32(v[j].y);
        o.z = f2tf32(v[j].z); o.w = f2tf32(v[j].w);
        *reinterpret_cast<uint4*>(g_xr + i0 + j * 4) = o;
    }
}

__global__ void round_w1(const float* __restrict__ P, const float* __restrict__ Wb,
                         const float* __restrict__ Wa)
{
    const float* src; float* dst;
    switch (blockIdx.y) {
        case 0: src = P;  dst = g_Pr;  break;
        case 1: src = Wb; dst = g_Wbr; break;
        default: src = Wa; dst = g_War; break;
    }
    const int i0 = (blockIdx.x * blockDim.x + threadIdx.x) * 16;
    float4 v[4];
#pragma unroll
    for (int j = 0; j < 4; j++)
        v[j] = *reinterpret_cast<const float4*>(src + i0 + j * 4);
#pragma unroll
    for (int j = 0; j < 4; j++) {
        uint4 o;
        o.x = f2tf32(v[j].x); o.y = f2tf32(v[j].y);
        o.z = f2tf32(v[j].z); o.w = f2tf32(v[j].w);
        *reinterpret_cast<uint4*>(dst + i0 + j * 4) = o;
    }
}

__global__ void round_w2(const float* __restrict__ Wr, const float* __restrict__ Wp)
{
    const float* src; float* dst; int n;
    if (blockIdx.y == 0) { src = Wr; dst = g_Wrr; n = DD*3*DD; }
    else                 { src = Wp; dst = g_Wpr; n = DD*DD; }
    const int i0 = (blockIdx.x * blockDim.x + threadIdx.x) * 16;
    if (i0 < n) {
        float4 v[4];
#pragma unroll
        for (int j = 0; j < 4; j++)
            v[j] = *reinterpret_cast<const float4*>(src + i0 + j * 4);
#pragma unroll
        for (int j = 0; j < 4; j++) {
            uint4 o;
            o.x = f2tf32(v[j].x); o.y = f2tf32(v[j].y);
            o.z = f2tf32(v[j].z); o.w = f2tf32(v[j].w);
            *reinterpret_cast<uint4*>(dst + i0 + j * 4) = o;
        }
    }
}

extern "C" void kernel_launch(void* const* d_in, const int* in_sizes, int n_in,
                              void* d_out, int out_size)
{
    const float* x          = (const float*)d_in[0];
    const float* f_prev     = (const float*)d_in[1];
    const float* s_prev     = (const float*)d_in[2];
    const float* w_lambda   = (const float*)d_in[3];
    const float* P_lambda_w = (const float*)d_in[4];
    const float* W_beta_w   = (const float*)d_in[5];
    const float* W_alpha_w  = (const float*)d_in[6];
    const float* W_alpha_b  = (const float*)d_in[7];
    const float* W_rho_w    = (const float*)d_in[8];
    const float* W_rho_b    = (const float*)d_in[9];
    const float* out_proj_w = (const float*)d_in[10];
    const float* res_scale  = (const float*)d_in[11];
    float* out = (float*)d_out;

    cudaFuncSetAttribute(rsp_gemm<0>, cudaFuncAttributeMaxDynamicSharedMemorySize, SMEMB);
    cudaFuncSetAttribute(rsp_gemm<1>, cudaFuncAttributeMaxDynamicSharedMemorySize, SMEMB);
    cudaFuncSetAttribute(rsp_gemm<2>, cudaFuncAttributeMaxDynamicSharedMemorySize, SMEMB);

    // 0) round ALL GEMM operands to tf32 (64 B/thread)
    round_x <<<MM*DD/16/256, 256>>>(x);
    round_w1<<<dim3(DD*DD/16/256, 3), 256>>>(P_lambda_w, W_beta_w, W_alpha_w);
    round_w2<<<dim3(DD*3*DD/16/256, 2), 256>>>(W_rho_w, out_proj_w);

    dim3 blk(256);
    // 1) lambda / beta-gate / alpha GEMMs  (launch #4 -> profiled)
    rsp_gemm<0><<<dim3(DD/BN, MM/BM, 3), blk, SMEMB>>>(
        x, w_lambda, W_alpha_b, nullptr, nullptr, nullptr);

    // 2) chunked parallel scan (3 passes)
    int write_tail = (out_size >= (int)((size_t)MM*DD + 2*NCH)) ? 1 : 0;
    scan_p1<<<dim3(NCH/256, CH), 256>>>();
    scan_p2<<<NCH/256, 256>>>(f_prev, s_prev, out, write_tail);
    scan_p3<<<dim3(NCH/256, CH), 256>>>();

    // 3) rho GEMM over virtual concat [f, s, x], mixes h = s + rho*(f-s)
    rsp_gemm<1><<<dim3(DD/BN, MM/BM, 1), blk, SMEMB>>>(
        x, nullptr, nullptr, W_rho_b, nullptr, nullptr);

    // 4) output projection + residual
    rsp_gemm<2><<<dim3(DD/BN, MM/BM, 1), blk, SMEMB>>>(
        x, nullptr, nullptr, nullptr, res_scale, out);
}

// round 16
// speedup vs baseline: 1.0031x; 1.0031x over previous
#include <cuda_runtime.h>
#include <math.h>
#include <stdint.h>

// Problem dims (fixed by setup_inputs)
#define BB 4
#define LL 2048
#define DD 1024
#define MM (BB*LL)   // 8192
#define NCH (BB*DD)  // 4096 channels
#define CH  32       // scan chunks
#define CL  (LL/CH)  // 64 steps per chunk

// Scratch (device globals: allowed; runtime alloc is not)
__device__ float g_lam[(size_t)MM*DD];
__device__ float g_b[(size_t)MM*DD];
__device__ float g_alpha[(size_t)MM*DD];
__device__ float g_f[(size_t)MM*DD];
__device__ float g_s[(size_t)MM*DD];
__device__ float g_h[(size_t)MM*DD];
// tf32-rounded operand copies (composed RNA rounding -> rel_err 2.8e-4)
__device__ float g_xr[(size_t)MM*DD];
__device__ float g_Pr[(size_t)DD*DD];
__device__ float g_Wbr[(size_t)DD*DD];
__device__ float g_War[(size_t)DD*DD];
__device__ float g_Wrr[(size_t)DD*3*DD];
__device__ float g_Wpr[(size_t)DD*DD];
// scan chunk maps + entry states
__device__ float p_A[CH*NCH], p_B0[CH*NCH], p_C[CH*NCH], p_D[CH*NCH], p_E[CH*NCH];
__device__ float e_f[CH*NCH], e_s[CH*NCH];

// ---------------- helpers ----------------
__device__ __forceinline__ uint32_t smem_u32(const void* p) {
    uint32_t a;
    asm("{ .reg .u64 t; cvta.to.shared.u64 t, %1; cvt.u32.u64 %0, t; }" : "=r"(a) : "l"(p));
    return a;
}

__device__ __forceinline__ uint32_t f2tf32(float f) {
    uint32_t r;
    asm("cvt.rna.tf32.f32 %0, %1;" : "=r"(r) : "f"(f));
    return r;
}

__device__ __forceinline__ void mma8(float c[4], const uint32_t a[4], const uint32_t b[2]) {
    asm volatile(
        "mma.sync.aligned.m16n8k8.row.col.f32.tf32.tf32.f32 "
        "{%0,%1,%2,%3},{%4,%5,%6,%7},{%8,%9},{%0,%1,%2,%3};\n"
        : "+f"(c[0]), "+f"(c[1]), "+f"(c[2]), "+f"(c[3])
        : "r"(a[0]), "r"(a[1]), "r"(a[2]), "r"(a[3]), "r"(b[0]), "r"(b[1]));
}

#define LDSM4(r0, r1, r2, r3, addr)                                            \
    asm volatile("ldmatrix.sync.aligned.m8n8.x4.shared.b16 {%0,%1,%2,%3},[%4];" \
        : "=r"(r0), "=r"(r1), "=r"(r2), "=r"(r3) : "r"(addr))

#define CP16(dst, src)                                                         \
    asm volatile("cp.async.cg.shared.global [%0], [%1], 16;"                   \
                 :: "r"(dst), "l"(src) : "memory")
#define CP_COMMIT() asm volatile("cp.async.commit_group;" ::: "memory")
#define CP_WAIT1()  asm volatile("cp.async.wait_group 1;" ::: "memory")
#define CP_WAIT0()  asm volatile("cp.async.wait_group 0;" ::: "memory")

__device__ __forceinline__ float fsig(float v) { return 1.0f / (1.0f + __expf(-v)); }

// ---------------- GEMM config ----------------
constexpr int BM = 128, BN = 128, BK = 32, STAGES = 3;
constexpr int ROWB   = 144;             // bytes per smem row (32 u32 + 4 pad)
constexpr int ATILE  = 128 * ROWB;      // 18432 B
constexpr int STAGEB = 2 * ATILE;       // A+B per stage (36864)
constexpr int SMEMB  = STAGES * STAGEB; // 110592 B -> 2 CTAs/SM

// MODE 0: Y = xr @ Wr^T, Wr in {g_Pr(z0), g_Wbr(z1), g_War(z2)} -> lam/b/alpha
// MODE 1: rho = sigmoid([f,s,xr] @ g_Wrr^T + b); g_h = s + rho*(f-s)
// MODE 2: out = x + res_scale * (g_h @ g_Wpr^T)
template<int MODE>
__global__ void __launch_bounds__(256, 2)
rsp_gemm(const float* __restrict__ x,
         const float* __restrict__ bias0, const float* __restrict__ bias2,
         const float* __restrict__ rho_b, const float* __restrict__ res_scale,
         float* __restrict__ dout)
{
    extern __shared__ char smem[];
    const uint32_t sb = smem_u32(smem);
    const int t = threadIdx.x;
    const int lane = t & 31, wid = t >> 5;
    const int bm = blockIdx.y * BM;
    const int bn = blockIdx.x * BN;

    constexpr int K    = (MODE == 1) ? 3072 : 1024;
    constexpr int KT   = K / BK;
    constexpr int LDB_ = (MODE == 1) ? 3072 : 1024;

    const float* Wsel;
    if (MODE == 0)
        Wsel = (blockIdx.z == 0) ? g_Pr : ((blockIdx.z == 1) ? g_Wbr : g_War);
    else if (MODE == 1)
        Wsel = g_Wrr;
    else
        Wsel = g_Wpr;

    // ---- async loader mapping: 256 threads, 2 threads per row, 4x16B each
    const int lrow = t >> 1;           // 0..127
    const int lch  = (t & 1) * 4;      // element chunk base (x4 -> 0 or 16 elts)
    const uint32_t adst0 = sb + (uint32_t)lrow * ROWB + (uint32_t)lch * 16;
    const uint32_t bdst0 = adst0 + ATILE;
    const float* bsrc_row = Wsel + (size_t)(bn + lrow) * LDB_ + lch * 4;

    auto load_stage = [&](int kt) {
        const int st = kt % STAGES;
        const int k0 = kt * BK;
        const float* asrc; int acol = k0;
        if (MODE == 1) {
            if (k0 < 1024)      { asrc = g_f; }
            else if (k0 < 2048) { asrc = g_s;  acol = k0 - 1024; }
            else                { asrc = g_xr; acol = k0 - 2048; }
        } else if (MODE == 0) { asrc = g_xr; }
        else                  { asrc = g_h; }
        const float* ap = asrc + (size_t)(bm + lrow) * 1024 + acol + lch * 4;
        const uint32_t ad = adst0 + st * STAGEB;
#pragma unroll
        for (int i = 0; i < 4; i++) CP16(ad + i * 16, ap + i * 4);
        const float* bp = bsrc_row + k0;
        const uint32_t bd = bdst0 + st * STAGEB;
#pragma unroll
        for (int i = 0; i < 4; i++) CP16(bd + i * 16, bp + i * 4);
    };

    // ---- ldmatrix per-lane address bases
    const int wm = (wid >> 2) * 64;    // warp tile 64x32
    const int wn = (wid & 3) * 32;
    uint32_t aoff[4], boff[2];
    {
        const int ar = wm + ((lane >> 3) & 1) * 8 + (lane & 7);
        const uint32_t aq = (uint32_t)(lane >> 4) * 16;
#pragma unroll
        for (int mi = 0; mi < 4; mi++)
            aoff[mi] = sb + (uint32_t)(ar + mi * 16) * ROWB + aq;
        const int br = wn + ((lane >> 4) & 1) * 8 + (lane & 7);
        const uint32_t bq = (uint32_t)((lane >> 3) & 1) * 16;
#pragma unroll
        for (int np = 0; np < 2; np++)
            boff[np] = sb + ATILE + (uint32_t)(br + np * 16) * ROWB + bq;
    }

    float c[4][4][4];
#pragma unroll
    for (int i = 0; i < 4; i++)
#pragma unroll
        for (int j = 0; j < 4; j++)
#pragma unroll
            for (int r = 0; r < 4; r++) c[i][j][r] = 0.f;

    // fragment double buffers (ks-level software pipeline)
    uint32_t af[2][4][4], bfr[2][4][2];

    auto ldsm_frag = [&](uint32_t stb, int ks, int buf) {
        const uint32_t o = stb + (uint32_t)ks * 32;
#pragma unroll
        for (int mi = 0; mi < 4; mi++)
            LDSM4(af[buf][mi][0], af[buf][mi][1], af[buf][mi][2], af[buf][mi][3],
                  aoff[mi] + o);
#pragma unroll
        for (int np = 0; np < 2; np++) {
            uint32_t r0, r1, r2, r3;
            LDSM4(r0, r1, r2, r3, boff[np] + o);
            bfr[buf][2*np][0]   = r0; bfr[buf][2*np][1]   = r1;
            bfr[buf][2*np+1][0] = r2; bfr[buf][2*np+1][1] = r3;
        }
    };

    // preamble: stages 0 and 1 in flight; fragments for (stage0, ks0) in regs
    load_stage(0); CP_COMMIT();
    load_stage(1); CP_COMMIT();
    CP_WAIT1();          // stage 0 landed
    __syncthreads();     // publish to all warps
    ldsm_frag(0, 0, 0);

    // steady state at top of kt: stage kt in smem (published), stage kt+1
    // committed; fragments (kt, ks0) already in buf (ks parity 0).
    // (R9/R13/R14 structure — measured best across all variants tried.)
#pragma unroll 1
    for (int kt = 0; kt < KT; kt++) {
        const uint32_t stb = (uint32_t)(kt % STAGES) * STAGEB;
#pragma unroll
        for (int ks = 0; ks < 4; ks++) {
            const int cur = ks & 1;
            if (ks < 3) {
                ldsm_frag(stb, ks + 1, cur ^ 1);    // prefetch next ks
            } else {
                // tile boundary, hidden behind the ks=3 MMA block below.
                if (kt + 2 < KT) {
                    load_stage(kt + 2);
                    CP_COMMIT();
                    CP_WAIT1();      // pending <=1 (stage kt+2) => kt+1 landed
                } else {
                    CP_WAIT0();      // tail: drain everything
                }
                __syncthreads();     // publish stage kt+1 across warps
                if (kt + 1 < KT)
                    ldsm_frag((uint32_t)((kt + 1) % STAGES) * STAGEB, 0, cur ^ 1);
            }
#pragma unroll
            for (int mi = 0; mi < 4; mi++)
#pragma unroll
                for (int ni = 0; ni < 4; ni++)
                    mma8(c[mi][ni], af[cur][mi], bfr[cur][ni]);
        }
    }

    // ---------------- epilogue ----------------
    const int g = lane >> 2, tg = lane & 3;
    const float rs = (MODE == 2) ? res_scale[0] : 0.f;
#pragma unroll
    for (int mi = 0; mi < 4; mi++) {
#pragma unroll
        for (int r2 = 0; r2 < 2; r2++) {
            const int m = bm + wm + mi * 16 + g + r2 * 8;
#pragma unroll
            for (int ni = 0; ni < 4; ni++) {
                const int e = bn + wn + ni * 8 + tg * 2;
                const size_t idx = (size_t)m * DD + e;
                const float v0 = c[mi][ni][r2 * 2 + 0];
                const float v1 = c[mi][ni][r2 * 2 + 1];
                if (MODE == 0) {
                    if (blockIdx.z == 0) {
                        float2 bp = *reinterpret_cast<const float2*>(bias0 + e);
                        float l0 = fminf(fmaxf(bp.x + v0, -4.f), 4.f);
                        float l1 = fminf(fmaxf(bp.y + v1, -4.f), 4.f);
                        float2 o;
                        o.x = fminf(fmaxf(__expf(-__expf(l0)), 0.001f), 0.999f);
                        o.y = fminf(fmaxf(__expf(-__expf(l1)), 0.001f), 0.999f);
                        *reinterpret_cast<float2*>(g_lam + idx) = o;
                    } else if (blockIdx.z == 1) {
                        float2 o;
                        o.x = v0 * fsig(v0) + 0.1f * __sinf(v0);
                        o.y = v1 * fsig(v1) + 0.1f * __sinf(v1);
                        *reinterpret_cast<float2*>(g_b + idx) = o;
                    } else {
                        float2 bp = *reinterpret_cast<const float2*>(bias2 + e);
                        float2 o;
                        o.x = fsig(v0 + bp.x);
                        o.y = fsig(v1 + bp.y);
                        *reinterpret_cast<float2*>(g_alpha + idx) = o;
                    }
                } else if (MODE == 1) {
                    float2 bp = *reinterpret_cast<const float2*>(rho_b + e);
                    float2 fv = *reinterpret_cast<const float2*>(g_f + idx);
                    float2 sv = *reinterpret_cast<const float2*>(g_s + idx);
                    float h0 = sv.x + fsig(v0 + bp.x) * (fv.x - sv.x);
                    float h1 = sv.y + fsig(v1 + bp.y) * (fv.y - sv.y);
                    // round at write: feeds the MODE2 GEMM as an A operand
                    uint2 o;
                    o.x = f2tf32(h0); o.y = f2tf32(h1);
                    *reinterpret_cast<uint2*>(g_h + idx) = o;
                } else {
                    float2 xv = *reinterpret_cast<const float2*>(x + idx);
                    float2 o;
                    o.x = xv.x + rs * v0;
                    o.y = xv.y + rs * v1;
                    *reinterpret_cast<float2*>(dout + idx) = o;
                }
            }
        }
    }
}

// ---------------- chunked parallel scan ----------------
// f_t = lam_t*f_{t-1} + b_t ; s_t = (1-a_t)*s_{t-1} + a_t*f_t
// Chunk map: f_out = A*f_in + B0 ; s_out = C*f_in + D*s_in + E
__global__ void __launch_bounds__(256)
scan_p1()
{
    const int ch    = blockIdx.x * 256 + threadIdx.x;  // 0..4095
    const int chunk = blockIdx.y;                       // 0..31
    const int b = ch / DD, d = ch % DD;
    const size_t base = (size_t)b * LL * DD + (size_t)(chunk * CL) * DD + d;

    float aF = 1.f, cF = 0.f, cS = 0.f, dS = 1.f, ee = 0.f;
#pragma unroll 16
    for (int u = 0; u < CL; u++) {
        const size_t i = base + (size_t)u * DD;
        const float lam = g_lam[i];
        const float bv  = g_b[i];
        const float al  = g_alpha[i];
        aF = lam * aF;
        cF = fmaf(lam, cF, bv);
        const float om = 1.f - al;
        cS = fmaf(om, cS, al * aF);
        dS = om * dS;
        ee = fmaf(om, ee, al * cF);
    }
    const int o = chunk * NCH + ch;
    p_A[o] = aF; p_B0[o] = cF; p_C[o] = cS; p_D[o] = dS; p_E[o] = ee;
}

// Pass 2: fold 32 chunk maps per channel, software-prefetched ping-pong.
__global__ void __launch_bounds__(256)
scan_p2(const float* __restrict__ f_prev, const float* __restrict__ s_prev,
        float* __restrict__ dout, int write_tail)
{
    const int ch = blockIdx.x * 256 + threadIdx.x;  // 0..4095
    float f = f_prev[ch], s = s_prev[ch];

    constexpr int U = 8;                   // chunks per batch; CH/U = 4 batches
    float A0[U], B0_[U], C0[U], D0[U], E0[U];
    float A1[U], B1_[U], C1[U], D1[U], E1[U];

#define P2_FETCH(sfx, batch) do {                                              \
        const int base_o = (batch) * U * NCH + ch;                             \
        _Pragma("unroll")                                                      \
        for (int u = 0; u < U; u++) {                                          \
            A##sfx[u]  = p_A [base_o + u * NCH];                               \
            B##sfx##_[u] = p_B0[base_o + u * NCH];                             \
            C##sfx[u]  = p_C [base_o + u * NCH];                               \
            D##sfx[u]  = p_D [base_o + u * NCH];                               \
            E##sfx[u]  = p_E [base_o + u * NCH];                               \
        } } while (0)

#define P2_FOLD(sfx, batch) do {                                               \
        const int base_o = (batch) * U * NCH + ch;                             \
        _Pragma("unroll")                                                      \
        for (int u = 0; u < U; u++) {                                          \
            e_f[base_o + u * NCH] = f;                                         \
            e_s[base_o + u * NCH] = s;                                         \
            const float fn = fmaf(A##sfx[u], f, B##sfx##_[u]);                 \
            s = fmaf(C##sfx[u], f, fmaf(D##sfx[u], s, E##sfx[u]));             \
            f = fn;                                                            \
        } } while (0)

    P2_FETCH(0, 0);
#pragma unroll 1
    for (int p = 0; p < CH / (2 * U); p++) {    // 2 pairs of batches
        P2_FETCH(1, 2 * p + 1);
        P2_FOLD(0, 2 * p);
        if (2 * p + 2 < CH / U) P2_FETCH(0, 2 * p + 2);
        P2_FOLD(1, 2 * p + 1);
    }
#undef P2_FETCH
#undef P2_FOLD

    if (write_tail) {
        dout[(size_t)MM * DD + ch]           = f;   // f_states[:, -1, :]
        dout[(size_t)MM * DD + NCH + ch]     = s;   // s_states[:, -1, :]
    }
}

__global__ void __launch_bounds__(256)
scan_p3()
{
    const int ch    = blockIdx.x * 256 + threadIdx.x;
    const int chunk = blockIdx.y;
    const int b = ch / DD, d = ch % DD;
    const size_t base = (size_t)b * LL * DD + (size_t)(chunk * CL) * DD + d;

    const int o = chunk * NCH + ch;
    float f = e_f[o], s = e_s[o];
#pragma unroll 16
    for (int u = 0; u < CL; u++) {
        const size_t i = base + (size_t)u * DD;
        const float lam = g_lam[i];
        const float bv  = g_b[i];
        const float al  = g_alpha[i];
        f = fmaf(lam, f, bv);
        s = fmaf(al, f - s, s);
        g_f[i] = __uint_as_float(f2tf32(f));
        g_s[i] = __uint_as_float(f2tf32(s));
    }
}

// ---------------- tf32 pre-rounding (3 launches; gemm<0> stays launch #4) --
__global__ void round_x(const float* __restrict__ src)
{
    int i = (blockIdx.x * blockDim.x + threadIdx.x) * 4;
    float4 v = *reinterpret_cast<const float4*>(src + i);
    uint4 o;
    o.x = f2tf32(v.x); o.y = f2tf32(v.y);
    o.z = f2tf32(v.z); o.w = f2tf32(v.w);
    *reinterpret_cast<uint4*>(g_xr + i) = o;
}

__global__ void round_w1(const float* __restrict__ P, const float* __restrict__ Wb,
                         const float* __restrict__ Wa)
{
    const float* src; float* dst;
    switch (blockIdx.y) {
        case 0: src = P;  dst = g_Pr;  break;
        case 1: src = Wb; dst = g_Wbr; break;
        default: src = Wa; dst = g_War; break;
    }
    int i = (blockIdx.x * blockDim.x + threadIdx.x) * 4;
    float4 v = *reinterpret_cast<const float4*>(src + i);
    uint4 o;
    o.x = f2tf32(v.x); o.y = f2tf32(v.y);
    o.z = f2tf32(v.z); o.w = f2tf32(v.w);
    *reinterpret_cast<uint4*>(dst + i) = o;
}

__global__ void round_w2(const float* __restrict__ Wr, const float* __restrict__ Wp)
{
    const float* src; float* dst; int n;
    if (blockIdx.y == 0) { src = Wr; dst = g_Wrr; n = DD*3*DD; }
    else                 { src = Wp; dst = g_Wpr; n = DD*DD; }
    int i = (blockIdx.x * blockDim.x + threadIdx.x) * 4;
    if (i < n) {
        float4 v = *reinterpret_cast<const float4*>(src + i);
        uint4 o;
        o.x = f2tf32(v.x); o.y = f2tf32(v.y);
        o.z = f2tf32(v.z); o.w = f2tf32(v.w);
        *reinterpret_cast<uint4*>(dst + i) = o;
    }
}

extern "C" void kernel_launch(void* const* d_in, const int* in_sizes, int n_in,
                              void* d_out, int out_size)
{
    const float* x          = (const float*)d_in[0];
    const float* f_prev     = (const float*)d_in[1];
    const float* s_prev     = (const float*)d_in[2];
    const float* w_lambda   = (const float*)d_in[3];
    const float* P_lambda_w = (const float*)d_in[4];
    const float* W_beta_w   = (const float*)d_in[5];
    const float* W_alpha_w  = (const float*)d_in[6];
    const float* W_alpha_b  = (const float*)d_in[7];
    const float* W_rho_w    = (const float*)d_in[8];
    const float* W_rho_b    = (const float*)d_in[9];
    const float* out_proj_w = (const float*)d_in[10];
    const float* res_scale  = (const float*)d_in[11];
    float* out = (float*)d_out;

    cudaFuncSetAttribute(rsp_gemm<0>, cudaFuncAttributeMaxDynamicSharedMemorySize, SMEMB);
    cudaFuncSetAttribute(rsp_gemm<1>, cudaFuncAttributeMaxDynamicSharedMemorySize, SMEMB);
    cudaFuncSetAttribute(rsp_gemm<2>, cudaFuncAttributeMaxDynamicSharedMemorySize, SMEMB);

    // 0) round ALL GEMM operands to tf32
    round_x <<<MM*DD/4/256, 256>>>(x);
    round_w1<<<dim3(DD*DD/4/256, 3), 256>>>(P_lambda_w, W_beta_w, W_alpha_w);
    round_w2<<<dim3(DD*3*DD/4/256, 2), 256>>>(W_rho_w, out_proj_w);

    dim3 blk(256);
    // 1) lambda / beta-gate / alpha GEMMs  (launch #4 -> profiled)
    rsp_gemm<0><<<dim3(DD/BN, MM/BM, 3), blk, SMEMB>>>(
        x, w_lambda, W_alpha_b, nullptr, nullptr, nullptr);

    // 2) chunked parallel scan (3 passes)
    int write_tail = (out_size >= (int)((size_t)MM*DD + 2*NCH)) ? 1 : 0;
    scan_p1<<<dim3(NCH/256, CH), 256>>>();
    scan_p2<<<NCH/256, 256>>>(f_prev, s_prev, out, write_tail);
    scan_p3<<<dim3(NCH/256, CH), 256>>>();

    // 3) rho GEMM over virtual concat [f, s, x], mixes h = s + rho*(f-s)
    rsp_gemm<1><<<dim3(DD/BN, MM/BM, 1), blk, SMEMB>>>(
        x, nullptr, nullptr, W_rho_b, nullptr, nullptr);

    // 4) output projection + residual
    rsp_gemm<2><<<dim3(DD/BN, MM/BM, 1), blk, SMEMB>>>(
        x, nullptr, nullptr, nullptr, res_scale, out);
}

// round 17
// speedup vs baseline: 1.0153x; 1.0122x over previous
#include <cuda_runtime.h>
#include <math.h>
#include <stdint.h>

// Problem dims (fixed by setup_inputs)
#define BB 4
#define LL 2048
#define DD 1024
#define MM (BB*LL)   // 8192
#define NCH (BB*DD)  // 4096 channels
#define CH  32       // scan chunks
#define CL  (LL/CH)  // 64 steps per chunk

// Scratch (device globals: allowed; runtime alloc is not)
__device__ float g_lam[(size_t)MM*DD];
__device__ float g_b[(size_t)MM*DD];
__device__ float g_alpha[(size_t)MM*DD];
__device__ float g_f[(size_t)MM*DD];
__device__ float g_s[(size_t)MM*DD];
__device__ float g_h[(size_t)MM*DD];
// tf32-rounded WEIGHT copies (RNA). x is streamed raw: HMMA truncates the
// operand mantissa (RZ) — measured rel_err 6.37e-4 (R10), deterministic,
// 36% margin under the 1e-3 threshold. Dropping round_x saves ~38us/call.
__device__ float g_Pr[(size_t)DD*DD];
__device__ float g_Wbr[(size_t)DD*DD];
__device__ float g_War[(size_t)DD*DD];
__device__ float g_Wrr[(size_t)DD*3*DD];
__device__ float g_Wpr[(size_t)DD*DD];
// scan chunk maps + entry states
__device__ float p_A[CH*NCH], p_B0[CH*NCH], p_C[CH*NCH], p_D[CH*NCH], p_E[CH*NCH];
__device__ float e_f[CH*NCH], e_s[CH*NCH];

// ---------------- helpers ----------------
__device__ __forceinline__ uint32_t smem_u32(const void* p) {
    uint32_t a;
    asm("{ .reg .u64 t; cvta.to.shared.u64 t, %1; cvt.u32.u64 %0, t; }" : "=r"(a) : "l"(p));
    return a;
}

__device__ __forceinline__ uint32_t f2tf32(float f) {
    uint32_t r;
    asm("cvt.rna.tf32.f32 %0, %1;" : "=r"(r) : "f"(f));
    return r;
}

__device__ __forceinline__ void mma8(float c[4], const uint32_t a[4], const uint32_t b[2]) {
    asm volatile(
        "mma.sync.aligned.m16n8k8.row.col.f32.tf32.tf32.f32 "
        "{%0,%1,%2,%3},{%4,%5,%6,%7},{%8,%9},{%0,%1,%2,%3};\n"
        : "+f"(c[0]), "+f"(c[1]), "+f"(c[2]), "+f"(c[3])
        : "r"(a[0]), "r"(a[1]), "r"(a[2]), "r"(a[3]), "r"(b[0]), "r"(b[1]));
}

#define LDSM4(r0, r1, r2, r3, addr)                                            \
    asm volatile("ldmatrix.sync.aligned.m8n8.x4.shared.b16 {%0,%1,%2,%3},[%4];" \
        : "=r"(r0), "=r"(r1), "=r"(r2), "=r"(r3) : "r"(addr))

#define CP16(dst, src)                                                         \
    asm volatile("cp.async.cg.shared.global [%0], [%1], 16;"                   \
                 :: "r"(dst), "l"(src) : "memory")
#define CP_COMMIT() asm volatile("cp.async.commit_group;" ::: "memory")
#define CP_WAIT1()  asm volatile("cp.async.wait_group 1;" ::: "memory")
#define CP_WAIT0()  asm volatile("cp.async.wait_group 0;" ::: "memory")

__device__ __forceinline__ float fsig(float v) { return 1.0f / (1.0f + __expf(-v)); }

// ---------------- GEMM config ----------------
constexpr int BM = 128, BN = 128, BK = 32, STAGES = 3;
constexpr int ROWB   = 144;             // bytes per smem row (32 u32 + 4 pad)
constexpr int ATILE  = 128 * ROWB;      // 18432 B
constexpr int STAGEB = 2 * ATILE;       // A+B per stage (36864)
constexpr int SMEMB  = STAGES * STAGEB; // 110592 B -> 2 CTAs/SM

// MODE 0: Y = x @ Wr^T, Wr in {g_Pr(z0), g_Wbr(z1), g_War(z2)} -> lam/b/alpha
// MODE 1: rho = sigmoid([f,s,x] @ g_Wrr^T + b); g_h = s + rho*(f-s)
// MODE 2: out = x + res_scale * (g_h @ g_Wpr^T)
template<int MODE>
__global__ void __launch_bounds__(256, 2)
rsp_gemm(const float* __restrict__ x,
         const float* __restrict__ bias0, const float* __restrict__ bias2,
         const float* __restrict__ rho_b, const float* __restrict__ res_scale,
         float* __restrict__ dout)
{
    extern __shared__ char smem[];
    const uint32_t sb = smem_u32(smem);
    const int t = threadIdx.x;
    const int lane = t & 31, wid = t >> 5;
    const int bm = blockIdx.y * BM;
    const int bn = blockIdx.x * BN;

    constexpr int K    = (MODE == 1) ? 3072 : 1024;
    constexpr int KT   = K / BK;
    constexpr int LDB_ = (MODE == 1) ? 3072 : 1024;

    const float* Wsel;
    if (MODE == 0)
        Wsel = (blockIdx.z == 0) ? g_Pr : ((blockIdx.z == 1) ? g_Wbr : g_War);
    else if (MODE == 1)
        Wsel = g_Wrr;
    else
        Wsel = g_Wpr;

    // ---- async loader mapping: 256 threads, 2 threads per row, 4x16B each
    const int lrow = t >> 1;           // 0..127
    const int lch  = (t & 1) * 4;      // element chunk base (x4 -> 0 or 16 elts)
    const uint32_t adst0 = sb + (uint32_t)lrow * ROWB + (uint32_t)lch * 16;
    const uint32_t bdst0 = adst0 + ATILE;
    const float* bsrc_row = Wsel + (size_t)(bn + lrow) * LDB_ + lch * 4;

    auto load_stage = [&](int kt) {
        const int st = kt % STAGES;
        const int k0 = kt * BK;
        const float* asrc; int acol = k0;
        if (MODE == 1) {
            if (k0 < 1024)      { asrc = g_f; }
            else if (k0 < 2048) { asrc = g_s; acol = k0 - 1024; }
            else                { asrc = x;   acol = k0 - 2048; }
        } else if (MODE == 0) { asrc = x; }
        else                  { asrc = g_h; }
        const float* ap = asrc + (size_t)(bm + lrow) * 1024 + acol + lch * 4;
        const uint32_t ad = adst0 + st * STAGEB;
#pragma unroll
        for (int i = 0; i < 4; i++) CP16(ad + i * 16, ap + i * 4);
        const float* bp = bsrc_row + k0;
        const uint32_t bd = bdst0 + st * STAGEB;
#pragma unroll
        for (int i = 0; i < 4; i++) CP16(bd + i * 16, bp + i * 4);
    };

    // ---- ldmatrix per-lane address bases
    const int wm = (wid >> 2) * 64;    // warp tile 64x32
    const int wn = (wid & 3) * 32;
    uint32_t aoff[4], boff[2];
    {
        const int ar = wm + ((lane >> 3) & 1) * 8 + (lane & 7);
        const uint32_t aq = (uint32_t)(lane >> 4) * 16;
#pragma unroll
        for (int mi = 0; mi < 4; mi++)
            aoff[mi] = sb + (uint32_t)(ar + mi * 16) * ROWB + aq;
        const int br = wn + ((lane >> 4) & 1) * 8 + (lane & 7);
        const uint32_t bq = (uint32_t)((lane >> 3) & 1) * 16;
#pragma unroll
        for (int np = 0; np < 2; np++)
            boff[np] = sb + ATILE + (uint32_t)(br + np * 16) * ROWB + bq;
    }

    float c[4][4][4];
#pragma unroll
    for (int i = 0; i < 4; i++)
#pragma unroll
        for (int j = 0; j < 4; j++)
#pragma unroll
            for (int r = 0; r < 4; r++) c[i][j][r] = 0.f;

    // fragment double buffers (ks-level software pipeline)
    uint32_t af[2][4][4], bfr[2][4][2];

    auto ldsm_frag = [&](uint32_t stb, int ks, int buf) {
        const uint32_t o = stb + (uint32_t)ks * 32;
#pragma unroll
        for (int mi = 0; mi < 4; mi++)
            LDSM4(af[buf][mi][0], af[buf][mi][1], af[buf][mi][2], af[buf][mi][3],
                  aoff[mi] + o);
#pragma unroll
        for (int np = 0; np < 2; np++) {
            uint32_t r0, r1, r2, r3;
            LDSM4(r0, r1, r2, r3, boff[np] + o);
            bfr[buf][2*np][0]   = r0; bfr[buf][2*np][1]   = r1;
            bfr[buf][2*np+1][0] = r2; bfr[buf][2*np+1][1] = r3;
        }
    };

    // preamble: stages 0 and 1 in flight; fragments for (stage0, ks0) in regs
    load_stage(0); CP_COMMIT();
    load_stage(1); CP_COMMIT();
    CP_WAIT1();          // stage 0 landed
    __syncthreads();     // publish to all warps
    ldsm_frag(0, 0, 0);

    // steady state at top of kt: stage kt in smem (published), stage kt+1
    // committed; fragments (kt, ks0) already in buf (ks parity 0).
    // (R9/R13/R14 structure — measured best across all variants tried.)
#pragma unroll 1
    for (int kt = 0; kt < KT; kt++) {
        const uint32_t stb = (uint32_t)(kt % STAGES) * STAGEB;
#pragma unroll
        for (int ks = 0; ks < 4; ks++) {
            const int cur = ks & 1;
            if (ks < 3) {
                ldsm_frag(stb, ks + 1, cur ^ 1);    // prefetch next ks
            } else {
                // tile boundary, hidden behind the ks=3 MMA block below.
                if (kt + 2 < KT) {
                    load_stage(kt + 2);
                    CP_COMMIT();
                    CP_WAIT1();      // pending <=1 (stage kt+2) => kt+1 landed
                } else {
                    CP_WAIT0();      // tail: drain everything
                }
                __syncthreads();     // publish stage kt+1 across warps
                if (kt + 1 < KT)
                    ldsm_frag((uint32_t)((kt + 1) % STAGES) * STAGEB, 0, cur ^ 1);
            }
#pragma unroll
            for (int mi = 0; mi < 4; mi++)
#pragma unroll
                for (int ni = 0; ni < 4; ni++)
                    mma8(c[mi][ni], af[cur][mi], bfr[cur][ni]);
        }
    }

    // ---------------- epilogue ----------------
    const int g = lane >> 2, tg = lane & 3;
    const float rs = (MODE == 2) ? res_scale[0] : 0.f;
#pragma unroll
    for (int mi = 0; mi < 4; mi++) {
#pragma unroll
        for (int r2 = 0; r2 < 2; r2++) {
            const int m = bm + wm + mi * 16 + g + r2 * 8;
#pragma unroll
            for (int ni = 0; ni < 4; ni++) {
                const int e = bn + wn + ni * 8 + tg * 2;
                const size_t idx = (size_t)m * DD + e;
                const float v0 = c[mi][ni][r2 * 2 + 0];
                const float v1 = c[mi][ni][r2 * 2 + 1];
                if (MODE == 0) {
                    if (blockIdx.z == 0) {
                        float2 bp = *reinterpret_cast<const float2*>(bias0 + e);
                        float l0 = fminf(fmaxf(bp.x + v0, -4.f), 4.f);
                        float l1 = fminf(fmaxf(bp.y + v1, -4.f), 4.f);
                        float2 o;
                        o.x = fminf(fmaxf(__expf(-__expf(l0)), 0.001f), 0.999f);
                        o.y = fminf(fmaxf(__expf(-__expf(l1)), 0.001f), 0.999f);
                        *reinterpret_cast<float2*>(g_lam + idx) = o;
                    } else if (blockIdx.z == 1) {
                        float2 o;
                        o.x = v0 * fsig(v0) + 0.1f * __sinf(v0);
                        o.y = v1 * fsig(v1) + 0.1f * __sinf(v1);
                        *reinterpret_cast<float2*>(g_b + idx) = o;
                    } else {
                        float2 bp = *reinterpret_cast<const float2*>(bias2 + e);
                        float2 o;
                        o.x = fsig(v0 + bp.x);
                        o.y = fsig(v1 + bp.y);
                        *reinterpret_cast<float2*>(g_alpha + idx) = o;
                    }
                } else if (MODE == 1) {
                    float2 bp = *reinterpret_cast<const float2*>(rho_b + e);
                    float2 fv = *reinterpret_cast<const float2*>(g_f + idx);
                    float2 sv = *reinterpret_cast<const float2*>(g_s + idx);
                    float h0 = sv.x + fsig(v0 + bp.x) * (fv.x - sv.x);
                    float h1 = sv.y + fsig(v1 + bp.y) * (fv.y - sv.y);
                    // round at write: feeds the MODE2 GEMM as an A operand
                    uint2 o;
                    o.x = f2tf32(h0); o.y = f2tf32(h1);
                    *reinterpret_cast<uint2*>(g_h + idx) = o;
                } else {
                    float2 xv = *reinterpret_cast<const float2*>(x + idx);
                    float2 o;
                    o.x = xv.x + rs * v0;
                    o.y = xv.y + rs * v1;
                    *reinterpret_cast<float2*>(dout + idx) = o;
                }
            }
        }
    }
}

// ---------------- chunked parallel scan ----------------
// f_t = lam_t*f_{t-1} + b_t ; s_t = (1-a_t)*s_{t-1} + a_t*f_t
// Chunk map: f_out = A*f_in + B0 ; s_out = C*f_in + D*s_in + E
__global__ void __launch_bounds__(256)
scan_p1()
{
    const int ch    = blockIdx.x * 256 + threadIdx.x;  // 0..4095
    const int chunk = blockIdx.y;                       // 0..31
    const int b = ch / DD, d = ch % DD;
    const size_t base = (size_t)b * LL * DD + (size_t)(chunk * CL) * DD + d;

    float aF = 1.f, cF = 0.f, cS = 0.f, dS = 1.f, ee = 0.f;
#pragma unroll 16
    for (int u = 0; u < CL; u++) {
        const size_t i = base + (size_t)u * DD;
        const float lam = g_lam[i];
        const float bv  = g_b[i];
        const float al  = g_alpha[i];
        aF = lam * aF;
        cF = fmaf(lam, cF, bv);
        const float om = 1.f - al;
        cS = fmaf(om, cS, al * aF);
        dS = om * dS;
        ee = fmaf(om, ee, al * cF);
    }
    const int o = chunk * NCH + ch;
    p_A[o] = aF; p_B0[o] = cF; p_C[o] = cS; p_D[o] = dS; p_E[o] = ee;
}

// Pass 2: fold 32 chunk maps per channel, software-prefetched ping-pong.
__global__ void __launch_bounds__(256)
scan_p2(const float* __restrict__ f_prev, const float* __restrict__ s_prev,
        float* __restrict__ dout, int write_tail)
{
    const int ch = blockIdx.x * 256 + threadIdx.x;  // 0..4095
    float f = f_prev[ch], s = s_prev[ch];

    constexpr int U = 8;                   // chunks per batch; CH/U = 4 batches
    float A0[U], B0_[U], C0[U], D0[U], E0[U];
    float A1[U], B1_[U], C1[U], D1[U], E1[U];

#define P2_FETCH(sfx, batch) do {                                              \
        const int base_o = (batch) * U * NCH + ch;                             \
        _Pragma("unroll")                                                      \
        for (int u = 0; u < U; u++) {                                          \
            A##sfx[u]  = p_A [base_o + u * NCH];                               \
            B##sfx##_[u] = p_B0[base_o + u * NCH];                             \
            C##sfx[u]  = p_C [base_o + u * NCH];                               \
            D##sfx[u]  = p_D [base_o + u * NCH];                               \
            E##sfx[u]  = p_E [base_o + u * NCH];                               \
        } } while (0)

#define P2_FOLD(sfx, batch) do {                                               \
        const int base_o = (batch) * U * NCH + ch;                             \
        _Pragma("unroll")                                                      \
        for (int u = 0; u < U; u++) {                                          \
            e_f[base_o + u * NCH] = f;                                         \
            e_s[base_o + u * NCH] = s;                                         \
            const float fn = fmaf(A##sfx[u], f, B##sfx##_[u]);                 \
            s = fmaf(C##sfx[u], f, fmaf(D##sfx[u], s, E##sfx[u]));             \
            f = fn;                                                            \
        } } while (0)

    P2_FETCH(0, 0);
#pragma unroll 1
    for (int p = 0; p < CH / (2 * U); p++) {    // 2 pairs of batches
        P2_FETCH(1, 2 * p + 1);
        P2_FOLD(0, 2 * p);
        if (2 * p + 2 < CH / U) P2_FETCH(0, 2 * p + 2);
        P2_FOLD(1, 2 * p + 1);
    }
#undef P2_FETCH
#undef P2_FOLD

    if (write_tail) {
        dout[(size_t)MM * DD + ch]           = f;   // f_states[:, -1, :]
        dout[(size_t)MM * DD + NCH + ch]     = s;   // s_states[:, -1, :]
    }
}

__global__ void __launch_bounds__(256)
scan_p3()
{
    const int ch    = blockIdx.x * 256 + threadIdx.x;
    const int chunk = blockIdx.y;
    const int b = ch / DD, d = ch % DD;
    const size_t base = (size_t)b * LL * DD + (size_t)(chunk * CL) * DD + d;

    const int o = chunk * NCH + ch;
    float f = e_f[o], s = e_s[o];
#pragma unroll 16
    for (int u = 0; u < CL; u++) {
        const size_t i = base + (size_t)u * DD;
        const float lam = g_lam[i];
        const float bv  = g_b[i];
        const float al  = g_alpha[i];
        f = fmaf(lam, f, bv);
        s = fmaf(al, f - s, s);
        g_f[i] = __uint_as_float(f2tf32(f));
        g_s[i] = __uint_as_float(f2tf32(s));
    }
}

// ---------------- tf32 pre-rounding of WEIGHTS only (2 launches) ----------
__global__ void round_w1(const float* __restrict__ P, const float* __restrict__ Wb,
                         const float* __restrict__ Wa)
{
    const float* src; float* dst;
    switch (blockIdx.y) {
        case 0: src = P;  dst = g_Pr;  break;
        case 1: src = Wb; dst = g_Wbr; break;
        default: src = Wa; dst = g_War; break;
    }
    int i = (blockIdx.x * blockDim.x + threadIdx.x) * 4;
    float4 v = *reinterpret_cast<const float4*>(src + i);
    uint4 o;
    o.x = f2tf32(v.x); o.y = f2tf32(v.y);
    o.z = f2tf32(v.z); o.w = f2tf32(v.w);
    *reinterpret_cast<uint4*>(dst + i) = o;
}

__global__ void round_w2(const float* __restrict__ Wr, const float* __restrict__ Wp)
{
    const float* src; float* dst; int n;
    if (blockIdx.y == 0) { src = Wr; dst = g_Wrr; n = DD*3*DD; }
    else                 { src = Wp; dst = g_Wpr; n = DD*DD; }
    int i = (blockIdx.x * blockDim.x + threadIdx.x) * 4;
    if (i < n) {
        float4 v = *reinterpret_cast<const float4*>(src + i);
        uint4 o;
        o.x = f2tf32(v.x); o.y = f2tf32(v.y);
        o.z = f2tf32(v.z); o.w = f2tf32(v.w);
        *reinterpret_cast<uint4*>(dst + i) = o;
    }
}

extern "C" void kernel_launch(void* const* d_in, const int* in_sizes, int n_in,
                              void* d_out, int out_size)
{
    const float* x          = (const float*)d_in[0];
    const float* f_prev     = (const float*)d_in[1];
    const float* s_prev     = (const float*)d_in[2];
    const float* w_lambda   = (const float*)d_in[3];
    const float* P_lambda_w = (const float*)d_in[4];
    const float* W_beta_w   = (const float*)d_in[5];
    const float* W_alpha_w  = (const float*)d_in[6];
    const float* W_alpha_b  = (const float*)d_in[7];
    const float* W_rho_w    = (const float*)d_in[8];
    const float* W_rho_b    = (const float*)d_in[9];
    const float* out_proj_w = (const float*)d_in[10];
    const float* res_scale  = (const float*)d_in[11];
    float* out = (float*)d_out;

    cudaFuncSetAttribute(rsp_gemm<0>, cudaFuncAttributeMaxDynamicSharedMemorySize, SMEMB);
    cudaFuncSetAttribute(rsp_gemm<1>, cudaFuncAttributeMaxDynamicSharedMemorySize, SMEMB);
    cudaFuncSetAttribute(rsp_gemm<2>, cudaFuncAttributeMaxDynamicSharedMemorySize, SMEMB);

    // 0) round WEIGHTS to tf32 (x streamed raw; HMMA truncates -> rel_err 6.4e-4)
    round_w1<<<dim3(DD*DD/4/256, 3), 256>>>(P_lambda_w, W_beta_w, W_alpha_w);
    round_w2<<<dim3(DD*3*DD/4/256, 2), 256>>>(W_rho_w, out_proj_w);

    dim3 blk(256);
    // 1) lambda / beta-gate / alpha GEMMs
    rsp_gemm<0><<<dim3(DD/BN, MM/BM, 3), blk, SMEMB>>>(
        x, w_lambda, W_alpha_b, nullptr, nullptr, nullptr);

    // 2) chunked parallel scan (3 passes; scan_p1 is launch #4 -> profiled)
    int write_tail = (out_size >= (int)((size_t)MM*DD + 2*NCH)) ? 1 : 0;
    scan_p1<<<dim3(NCH/256, CH), 256>>>();
    scan_p2<<<NCH/256, 256>>>(f_prev, s_prev, out, write_tail);
    scan_p3<<<dim3(NCH/256, CH), 256>>>();

    // 3) rho GEMM over virtual concat [f, s, x], mixes h = s + rho*(f-s)
    rsp_gemm<1><<<dim3(DD/BN, MM/BM, 1), blk, SMEMB>>>(
        x, nullptr, nullptr, W_rho_b, nullptr, nullptr);

    // 4) output projection + residual
    rsp_gemm<2><<<dim3(DD/BN, MM/BM, 1), blk, SMEMB>>>(
        x, nullptr, nullptr, nullptr, res_scale, out);
}